// round 12
// baseline (speedup 1.0000x reference)
#include <cuda_runtime.h>
#include <cuda_fp16.h>
#include <cstdint>
#include <math.h>

#define NN 100000
#define EE 1600000
#define FIN 128
#define HD  64
#define CC  40
#define LL  6
#define NB  ((NN + 255) / 256)       // 391 scan blocks
#define CIMAX (EE + 3 * NN)          // padded colidx capacity

// ---------------- scratch (static device allocation; no cudaMalloc) ----------------
__device__ int    g_deg[NN];
__device__ int    g_rowptr[NN + 1];  // PADDED offsets (each node multiple of 4)
__device__ int    g_fill[NN];
__device__ float  g_dis[NN];
__device__ int    g_colidx[CIMAX];
__device__ int    g_bsum[NB];
__device__ int    g_boff[NB];
__device__ float  g_hn[(size_t)(NN + 1) * HD]; // +1: sentinel zero row (index NN)
__device__ __half g_h16[(size_t)NN * HD];      // post-relu layer output (fp16 GEMM A)
__device__ float  g_jk[(size_t)NN * HD];       // running JumpingKnowledge max (fp32)

// ---------------- graph preprocessing ----------------
__global__ void k_count(const int* __restrict__ dst) {
    int e4 = (blockIdx.x * blockDim.x + threadIdx.x) * 4;
    if (e4 < EE) {
        int4 d = *(const int4*)&dst[e4];
        atomicAdd(&g_deg[d.x], 1);
        atomicAdd(&g_deg[d.y], 1);
        atomicAdd(&g_deg[d.z], 1);
        atomicAdd(&g_deg[d.w], 1);
    }
}

__global__ void k_scan1() {
    __shared__ int wsum[8];
    int tid = threadIdx.x, lane = tid & 31, w = tid >> 5;
    int i = blockIdx.x * 256 + tid;
    int pd = (i < NN) ? ((g_deg[i] + 3) & ~3) : 0;   // padded degree
    int s = pd;
    #pragma unroll
    for (int off = 16; off; off >>= 1) s += __shfl_xor_sync(0xffffffffu, s, off);
    if (lane == 0) wsum[w] = s;
    __syncthreads();
    if (tid == 0) {
        int t = 0;
        #pragma unroll
        for (int k = 0; k < 8; k++) t += wsum[k];
        g_bsum[blockIdx.x] = t;
    }
}

__global__ void k_scan2() {
    __shared__ int sh[512];
    int tid = threadIdx.x;
    int v = (tid < NB) ? g_bsum[tid] : 0;
    sh[tid] = v;
    __syncthreads();
    #pragma unroll
    for (int off = 1; off < 512; off <<= 1) {
        int t = (tid >= off) ? sh[tid - off] : 0;
        __syncthreads();
        sh[tid] += t;
        __syncthreads();
    }
    if (tid < NB) g_boff[tid] = sh[tid] - v;   // exclusive
    if (tid == 511) g_rowptr[NN] = sh[511];    // total padded count
}

__global__ void k_scan3() {
    __shared__ int wsum[8];
    __shared__ int woff[8];
    int tid = threadIdx.x, lane = tid & 31, w = tid >> 5;
    int i = blockIdx.x * 256 + tid;
    int d  = (i < NN) ? g_deg[i] : 0;
    int pd = (d + 3) & ~3;
    int x = pd;
    #pragma unroll
    for (int off = 1; off < 32; off <<= 1) {
        int t = __shfl_up_sync(0xffffffffu, x, off);
        if (lane >= off) x += t;
    }
    if (lane == 31) wsum[w] = x;
    __syncthreads();
    if (w == 0 && lane < 8) {
        int v = wsum[lane];
        int y = v;
        #pragma unroll
        for (int off = 1; off < 8; off <<= 1) {
            int t = __shfl_up_sync(0xffu, y, off);
            if (lane >= off) y += t;
        }
        woff[lane] = y - v;   // exclusive over warps
    }
    __syncthreads();
    if (i < NN) {
        int excl = g_boff[blockIdx.x] + woff[w] + (x - pd);
        g_rowptr[i] = excl;
        g_fill[i]   = excl;
        g_dis[i]    = rsqrtf((float)(d + 1));   // +1: self loop
    }
}

__global__ void k_scatter(const int* __restrict__ src, const int* __restrict__ dst) {
    int e4 = (blockIdx.x * blockDim.x + threadIdx.x) * 4;
    if (e4 < EE) {
        int4 s = *(const int4*)&src[e4];
        int4 d = *(const int4*)&dst[e4];
        int p;
        p = atomicAdd(&g_fill[d.x], 1); g_colidx[p] = s.x;
        p = atomicAdd(&g_fill[d.y], 1); g_colidx[p] = s.y;
        p = atomicAdd(&g_fill[d.z], 1); g_colidx[p] = s.z;
        p = atomicAdd(&g_fill[d.w], 1); g_colidx[p] = s.w;
    }
}

// pad each node's edge list to its padded length with sentinel NN; zero sentinel hn row
__global__ void k_pad() {
    int i = blockIdx.x * 256 + threadIdx.x;
    if (i < NN) {
        int e = g_fill[i];           // rowptr[i] + deg[i]
        int pe = g_rowptr[i + 1];    // padded end (contiguous: next node's start)
        for (int p = e; p < pe; p++) g_colidx[p] = NN;
    }
    if (blockIdx.x == 0 && threadIdx.x < HD)
        g_hn[(size_t)NN * HD + threadIdx.x] = 0.f;
}

// ---------------- tensor-core GEMM:  hn[row,:] = dis[row] * fp16(A[row,:]) @ fp16(W) ----------------
__device__ __forceinline__ uint32_t smem_u32(const void* p) {
    return (uint32_t)__cvta_generic_to_shared(p);
}

#define AS_STRIDE 72
#define BS_STRIDE 72

template<int K, bool FROMX>
__global__ void k_gemm_mma(const float* __restrict__ Aext, const float* __restrict__ W) {
    __shared__ __half As[128][AS_STRIDE];
    __shared__ __half Bs[64][BS_STRIDE];

    int tid = threadIdx.x;
    int warp = tid >> 5, lane = tid & 31;
    int brow = blockIdx.x * 128;

    float d[8][4];
    #pragma unroll
    for (int i = 0; i < 8; i++)
        #pragma unroll
        for (int j = 0; j < 4; j++) d[i][j] = 0.f;

    for (int kc = 0; kc < K; kc += 64) {
        if (kc) __syncthreads();
        {
            int r = tid >> 1;
            int c0 = (tid & 1) * 32;
            int row = brow + r;
            if (FROMX) {
                #pragma unroll
                for (int i = 0; i < 8; i++) {
                    float4 v = make_float4(0.f, 0.f, 0.f, 0.f);
                    if (row < NN)
                        v = *(const float4*)&Aext[(size_t)row * K + kc + c0 + i * 4];
                    __half2 p0 = __floats2half2_rn(v.x, v.y);
                    __half2 p1 = __floats2half2_rn(v.z, v.w);
                    uint2 pk;
                    pk.x = *(unsigned int*)&p0;
                    pk.y = *(unsigned int*)&p1;
                    *(uint2*)&As[r][c0 + i * 4] = pk;
                }
            } else {
                #pragma unroll
                for (int i = 0; i < 4; i++) {
                    uint4 v = make_uint4(0, 0, 0, 0);
                    if (row < NN)
                        v = *(const uint4*)&g_h16[(size_t)row * K + kc + c0 + i * 8];
                    *(uint4*)&As[r][c0 + i * 8] = v;
                }
            }
        }
        {
            int r = tid >> 2;
            int c0 = (tid & 3) * 16;
            #pragma unroll
            for (int q = 0; q < 4; q++) {
                float4 v = *(const float4*)&W[(size_t)(kc + r) * HD + c0 + q * 4];
                __half2 p0 = __floats2half2_rn(v.x, v.y);
                __half2 p1 = __floats2half2_rn(v.z, v.w);
                uint2 pk;
                pk.x = *(unsigned int*)&p0;
                pk.y = *(unsigned int*)&p1;
                *(uint2*)&Bs[r][c0 + q * 4] = pk;
            }
        }
        __syncthreads();

        #pragma unroll
        for (int kk = 0; kk < 4; kk++) {
            uint32_t a0, a1, a2, a3;
            {
                int j = lane >> 3;
                uint32_t addr = smem_u32(&As[warp * 16 + (lane & 7) + 8 * (j & 1)]
                                            [kk * 16 + 8 * (j >> 1)]);
                asm volatile("ldmatrix.sync.aligned.m8n8.x4.shared.b16 {%0,%1,%2,%3}, [%4];"
                             : "=r"(a0), "=r"(a1), "=r"(a2), "=r"(a3) : "r"(addr));
            }
            #pragma unroll
            for (int nt = 0; nt < 8; nt += 2) {
                uint32_t b0, b1, b2, b3;
                int j = lane >> 3;
                uint32_t addr = smem_u32(&Bs[kk * 16 + (lane & 7) + 8 * (j & 1)]
                                            [nt * 8 + 8 * (j >> 1)]);
                asm volatile("ldmatrix.sync.aligned.m8n8.x4.trans.shared.b16 {%0,%1,%2,%3}, [%4];"
                             : "=r"(b0), "=r"(b1), "=r"(b2), "=r"(b3) : "r"(addr));
                asm volatile("mma.sync.aligned.m16n8k16.row.col.f32.f16.f16.f32 "
                             "{%0,%1,%2,%3}, {%4,%5,%6,%7}, {%8,%9}, {%0,%1,%2,%3};"
                             : "+f"(d[nt][0]), "+f"(d[nt][1]), "+f"(d[nt][2]), "+f"(d[nt][3])
                             : "r"(a0), "r"(a1), "r"(a2), "r"(a3), "r"(b0), "r"(b1));
                asm volatile("mma.sync.aligned.m16n8k16.row.col.f32.f16.f16.f32 "
                             "{%0,%1,%2,%3}, {%4,%5,%6,%7}, {%8,%9}, {%0,%1,%2,%3};"
                             : "+f"(d[nt+1][0]), "+f"(d[nt+1][1]), "+f"(d[nt+1][2]), "+f"(d[nt+1][3])
                             : "r"(a0), "r"(a1), "r"(a2), "r"(a3), "r"(b2), "r"(b3));
            }
        }
    }

    int g = lane >> 2, q = lane & 3;
    int row0 = brow + warp * 16 + g;
    int row1 = row0 + 8;
    float d0 = (row0 < NN) ? g_dis[row0] : 0.f;
    float d1 = (row1 < NN) ? g_dis[row1] : 0.f;
    #pragma unroll
    for (int nt = 0; nt < 8; nt++) {
        int c = nt * 8 + 2 * q;
        if (row0 < NN)
            *(float2*)&g_hn[(size_t)row0 * HD + c] = make_float2(d[nt][0] * d0, d[nt][1] * d0);
        if (row1 < NN)
            *(float2*)&g_hn[(size_t)row1 * HD + c] = make_float2(d[nt][2] * d1, d[nt][3] * d1);
    }
}

// ---------------- gather: paired-lane float4 gathers + aligned int4 colidx, pipelined ----------------
// lanes 0-15 gather even edge, lanes 16-31 odd edge; each lane owns 4 feature cols.
// Returns the full aggregated float4 (incl. self term) valid on lanes 0-15.
__device__ __forceinline__ float4 warp_gather_sum4(int v, int lane) {
    int beg = g_rowptr[v], end = g_rowptr[v + 1];   // both multiples of 4
    int col4 = (lane & 15) * 4;
    bool lo = lane < 16;
    float4 acc = make_float4(0.f, 0.f, 0.f, 0.f);

    int niter = (end - beg) >> 2;
    if (niter) {
        int4 c = *(const int4*)&g_colidx[beg];
        int p = beg + 4;
        for (int it = 1; it < niter; it++, p += 4) {
            int4 n = *(const int4*)&g_colidx[p];      // prefetch next 4 edges
            int u0 = lo ? c.x : c.y;
            int u1 = lo ? c.z : c.w;
            float4 t0 = *(const float4*)&g_hn[(size_t)u0 * HD + col4];
            float4 t1 = *(const float4*)&g_hn[(size_t)u1 * HD + col4];
            acc.x += t0.x + t1.x; acc.y += t0.y + t1.y;
            acc.z += t0.z + t1.z; acc.w += t0.w + t1.w;
            c = n;
        }
        int u0 = lo ? c.x : c.y;
        int u1 = lo ? c.z : c.w;
        float4 t0 = *(const float4*)&g_hn[(size_t)u0 * HD + col4];
        float4 t1 = *(const float4*)&g_hn[(size_t)u1 * HD + col4];
        acc.x += t0.x + t1.x; acc.y += t0.y + t1.y;
        acc.z += t0.z + t1.z; acc.w += t0.w + t1.w;
    }

    // fold odd-edge half onto lanes 0-15
    acc.x += __shfl_xor_sync(0xffffffffu, acc.x, 16);
    acc.y += __shfl_xor_sync(0xffffffffu, acc.y, 16);
    acc.z += __shfl_xor_sync(0xffffffffu, acc.z, 16);
    acc.w += __shfl_xor_sync(0xffffffffu, acc.w, 16);

    if (lo) {   // self-loop term
        float4 s = *(const float4*)&g_hn[(size_t)v * HD + col4];
        acc.x += s.x; acc.y += s.y; acc.z += s.z; acc.w += s.w;
    }
    return acc;
}

__global__ void __launch_bounds__(256, 8)
k_agg(const float* __restrict__ bias, int first) {
    int warp = (blockIdx.x * blockDim.x + threadIdx.x) >> 5;
    int lane = threadIdx.x & 31;
    if (warp >= NN) return;
    int v = warp;

    float4 acc = warp_gather_sum4(v, lane);
    if (lane < 16) {
        int col4 = lane * 4;
        float d = g_dis[v];
        float4 b = *(const float4*)&bias[col4];
        float h0 = fmaxf(fmaf(d, acc.x, b.x), 0.f);
        float h1 = fmaxf(fmaf(d, acc.y, b.y), 0.f);
        float h2 = fmaxf(fmaf(d, acc.z, b.z), 0.f);
        float h3 = fmaxf(fmaf(d, acc.w, b.w), 0.f);

        size_t fo = (size_t)v * HD + col4;
        __half2 p0 = __floats2half2_rn(h0, h1);
        __half2 p1 = __floats2half2_rn(h2, h3);
        uint2 pk;
        pk.x = *(unsigned int*)&p0;
        pk.y = *(unsigned int*)&p1;
        *(uint2*)&g_h16[fo] = pk;

        if (first) {
            *(float4*)&g_jk[fo] = make_float4(h0, h1, h2, h3);
        } else {
            float4 j = *(const float4*)&g_jk[fo];
            *(float4*)&g_jk[fo] = make_float4(fmaxf(j.x, h0), fmaxf(j.y, h1),
                                              fmaxf(j.z, h2), fmaxf(j.w, h3));
        }
    }
}

// ---------------- last layer fused with head ----------------
__global__ void __launch_bounds__(256, 8)
k_agg_proj(const float* __restrict__ bias,
           const float* __restrict__ fcw, const float* __restrict__ fcb,
           float* __restrict__ out) {
    __shared__ float Wsm[HD * CC];
    __shared__ float bsm[CC];
    int tid = threadIdx.x;
    for (int i = tid; i < HD * CC; i += blockDim.x) Wsm[i] = fcw[i];
    if (tid < CC) bsm[tid] = fcb[tid];
    __syncthreads();

    int warp = (blockIdx.x * blockDim.x + tid) >> 5;
    int lane = tid & 31;
    if (warp >= NN) return;
    int v = warp;

    float4 acc = warp_gather_sum4(v, lane);
    float4 jv = make_float4(0.f, 0.f, 0.f, 0.f);
    if (lane < 16) {
        int col4 = lane * 4;
        float d = g_dis[v];
        float4 b = *(const float4*)&bias[col4];
        float h0 = fmaxf(fmaf(d, acc.x, b.x), 0.f);
        float h1 = fmaxf(fmaf(d, acc.y, b.y), 0.f);
        float h2 = fmaxf(fmaf(d, acc.z, b.z), 0.f);
        float h3 = fmaxf(fmaf(d, acc.w, b.w), 0.f);
        float4 j = *(const float4*)&g_jk[(size_t)v * HD + col4];
        jv = make_float4(fmaxf(j.x, h0), fmaxf(j.y, h1), fmaxf(j.z, h2), fmaxf(j.w, h3));
    }

    // projection: jk cols live 4/lane on lanes 0-15
    bool act = lane < 20;
    int c0 = lane * 2;
    float a0 = 0.f, a1 = 0.f;
    #pragma unroll
    for (int k = 0; k < HD; k++) {
        float comp = ((k & 3) == 0) ? jv.x : ((k & 3) == 1) ? jv.y
                   : ((k & 3) == 2) ? jv.z : jv.w;             // compile-time select (unrolled)
        float hv = __shfl_sync(0xffffffffu, comp, k >> 2);
        if (act) {
            float2 w = *(const float2*)&Wsm[k * CC + c0];
            a0 = fmaf(hv, w.x, a0);
            a1 = fmaf(hv, w.y, a1);
        }
    }
    if (act) { a0 += bsm[c0]; a1 += bsm[c0 + 1]; }

    float m = act ? fmaxf(a0, a1) : -INFINITY;
    #pragma unroll
    for (int off = 16; off; off >>= 1) m = fmaxf(m, __shfl_xor_sync(0xffffffffu, m, off));
    float s = act ? (expf(a0 - m) + expf(a1 - m)) : 0.f;
    #pragma unroll
    for (int off = 16; off; off >>= 1) s += __shfl_xor_sync(0xffffffffu, s, off);
    float lse = m + logf(s);

    if (act) {
        float2 o = make_float2(a0 - lse, a1 - lse);
        *(float2*)&out[(size_t)v * CC + c0] = o;
    }
}

// ---------------- launch ----------------
extern "C" void kernel_launch(void* const* d_in, const int* in_sizes, int n_in,
                              void* d_out, int out_size) {
    const float* x   = (const float*)d_in[0];
    const int*   ei  = (const int*)  d_in[1];
    const float* W0  = (const float*)d_in[2];
    const float* Ws  = (const float*)d_in[3];
    const float* bs  = (const float*)d_in[4];
    const float* fcw = (const float*)d_in[5];
    const float* fcb = (const float*)d_in[6];
    float* out = (float*)d_out;

    const int* src = ei;         // edge_index[0]
    const int* dst = ei + EE;    // edge_index[1]

    int* degp;
    cudaGetSymbolAddress((void**)&degp, g_deg);

    // CSR build (padded to multiples of 4 per node)
    cudaMemsetAsync(degp, 0, NN * sizeof(int));
    k_count  <<<(EE / 4 + 255) / 256, 256>>>(dst);
    k_scan1  <<<NB, 256>>>();
    k_scan2  <<<1, 512>>>();
    k_scan3  <<<NB, 256>>>();
    k_scatter<<<(EE / 4 + 255) / 256, 256>>>(src, dst);
    k_pad    <<<NB, 256>>>();

    const int GEMM_GRID = (NN + 127) / 128;  // 782 (128-row tiles)
    const int AGG_GRID  = (NN + 7) / 8;      // 8 warps per 256-thread block

    // layer 0: x (N x 128) @ W0
    k_gemm_mma<FIN, true><<<GEMM_GRID, 256>>>(x, W0);
    k_agg<<<AGG_GRID, 256>>>(bs + 0 * HD, 1);

    // layers 1..4
    for (int l = 1; l < LL - 1; l++) {
        k_gemm_mma<HD, false><<<GEMM_GRID, 256>>>(nullptr, Ws + (size_t)(l - 1) * HD * HD);
        k_agg<<<AGG_GRID, 256>>>(bs + (size_t)l * HD, 0);
    }
    // layer 5: aggregation fused with projection head
    k_gemm_mma<HD, false><<<GEMM_GRID, 256>>>(nullptr, Ws + (size_t)(LL - 2) * HD * HD);
    k_agg_proj<<<AGG_GRID, 256>>>(bs + (size_t)(LL - 1) * HD, fcw, fcb, out);
}

// round 13
// speedup vs baseline: 1.0046x; 1.0046x over previous
#include <cuda_runtime.h>
#include <cuda_fp16.h>
#include <cstdint>
#include <math.h>

#define NN 100000
#define EE 1600000
#define FIN 128
#define HD  64
#define CC  40
#define LL  6
#define NB  ((NN + 255) / 256)       // 391 scan blocks
#define CIMAX (EE + 3 * NN)          // padded colidx capacity

// ---------------- scratch (static device allocation; no cudaMalloc) ----------------
__device__ int    g_deg[NN];
__device__ int    g_rowptr[NN + 1];  // PADDED offsets (each node multiple of 4)
__device__ int    g_fill[NN];
__device__ float  g_dis[NN];
__device__ int    g_colidx[CIMAX];
__device__ int    g_bsum[NB];
__device__ int    g_boff[NB];
__device__ float  g_hn[(size_t)(NN + 1) * HD]; // +1: sentinel zero row (index NN)
__device__ __half g_h16[(size_t)NN * HD];      // post-relu layer output (fp16 GEMM A)
__device__ float  g_jk[(size_t)NN * HD];       // running JumpingKnowledge max (fp32)

// ---------------- graph preprocessing ----------------
__global__ void k_count(const int* __restrict__ dst) {
    int e4 = (blockIdx.x * blockDim.x + threadIdx.x) * 4;
    if (e4 < EE) {
        int4 d = *(const int4*)&dst[e4];
        atomicAdd(&g_deg[d.x], 1);
        atomicAdd(&g_deg[d.y], 1);
        atomicAdd(&g_deg[d.z], 1);
        atomicAdd(&g_deg[d.w], 1);
    }
}

__global__ void k_scan1() {
    __shared__ int wsum[8];
    int tid = threadIdx.x, lane = tid & 31, w = tid >> 5;
    int i = blockIdx.x * 256 + tid;
    int pd = (i < NN) ? ((g_deg[i] + 3) & ~3) : 0;   // padded degree
    int s = pd;
    #pragma unroll
    for (int off = 16; off; off >>= 1) s += __shfl_xor_sync(0xffffffffu, s, off);
    if (lane == 0) wsum[w] = s;
    __syncthreads();
    if (tid == 0) {
        int t = 0;
        #pragma unroll
        for (int k = 0; k < 8; k++) t += wsum[k];
        g_bsum[blockIdx.x] = t;
    }
}

__global__ void k_scan2() {
    __shared__ int sh[512];
    int tid = threadIdx.x;
    int v = (tid < NB) ? g_bsum[tid] : 0;
    sh[tid] = v;
    __syncthreads();
    #pragma unroll
    for (int off = 1; off < 512; off <<= 1) {
        int t = (tid >= off) ? sh[tid - off] : 0;
        __syncthreads();
        sh[tid] += t;
        __syncthreads();
    }
    if (tid < NB) g_boff[tid] = sh[tid] - v;   // exclusive
    if (tid == 511) g_rowptr[NN] = sh[511];    // total padded count
}

__global__ void k_scan3() {
    __shared__ int wsum[8];
    __shared__ int woff[8];
    int tid = threadIdx.x, lane = tid & 31, w = tid >> 5;
    int i = blockIdx.x * 256 + tid;
    int d  = (i < NN) ? g_deg[i] : 0;
    int pd = (d + 3) & ~3;
    int x = pd;
    #pragma unroll
    for (int off = 1; off < 32; off <<= 1) {
        int t = __shfl_up_sync(0xffffffffu, x, off);
        if (lane >= off) x += t;
    }
    if (lane == 31) wsum[w] = x;
    __syncthreads();
    if (w == 0 && lane < 8) {
        int v = wsum[lane];
        int y = v;
        #pragma unroll
        for (int off = 1; off < 8; off <<= 1) {
            int t = __shfl_up_sync(0xffu, y, off);
            if (lane >= off) y += t;
        }
        woff[lane] = y - v;   // exclusive over warps
    }
    __syncthreads();
    if (i < NN) {
        int excl = g_boff[blockIdx.x] + woff[w] + (x - pd);
        g_rowptr[i] = excl;
        g_fill[i]   = excl;
        g_dis[i]    = rsqrtf((float)(d + 1));   // +1: self loop
    }
}

__global__ void k_scatter(const int* __restrict__ src, const int* __restrict__ dst) {
    int e4 = (blockIdx.x * blockDim.x + threadIdx.x) * 4;
    if (e4 < EE) {
        int4 s = *(const int4*)&src[e4];
        int4 d = *(const int4*)&dst[e4];
        int p;
        p = atomicAdd(&g_fill[d.x], 1); g_colidx[p] = s.x;
        p = atomicAdd(&g_fill[d.y], 1); g_colidx[p] = s.y;
        p = atomicAdd(&g_fill[d.z], 1); g_colidx[p] = s.z;
        p = atomicAdd(&g_fill[d.w], 1); g_colidx[p] = s.w;
    }
}

// pad each node's edge list to its padded length with sentinel NN; zero sentinel hn row
__global__ void k_pad() {
    int i = blockIdx.x * 256 + threadIdx.x;
    if (i < NN) {
        int e = g_fill[i];           // rowptr[i] + deg[i]
        int pe = g_rowptr[i + 1];    // padded end (contiguous: next node's start)
        for (int p = e; p < pe; p++) g_colidx[p] = NN;
    }
    if (blockIdx.x == 0 && threadIdx.x < HD)
        g_hn[(size_t)NN * HD + threadIdx.x] = 0.f;
}

// ---------------- tensor-core GEMM:  hn[row,:] = dis[row] * fp16(A[row,:]) @ fp16(W) ----------------
__device__ __forceinline__ uint32_t smem_u32(const void* p) {
    return (uint32_t)__cvta_generic_to_shared(p);
}

#define AS_STRIDE 72
#define BS_STRIDE 72

template<int K, bool FROMX>
__global__ void k_gemm_mma(const float* __restrict__ Aext, const float* __restrict__ W) {
    __shared__ __half As[128][AS_STRIDE];
    __shared__ __half Bs[64][BS_STRIDE];

    int tid = threadIdx.x;
    int warp = tid >> 5, lane = tid & 31;
    int brow = blockIdx.x * 128;

    float d[8][4];
    #pragma unroll
    for (int i = 0; i < 8; i++)
        #pragma unroll
        for (int j = 0; j < 4; j++) d[i][j] = 0.f;

    for (int kc = 0; kc < K; kc += 64) {
        if (kc) __syncthreads();
        {
            int r = tid >> 1;
            int c0 = (tid & 1) * 32;
            int row = brow + r;
            if (FROMX) {
                #pragma unroll
                for (int i = 0; i < 8; i++) {
                    float4 v = make_float4(0.f, 0.f, 0.f, 0.f);
                    if (row < NN)
                        v = *(const float4*)&Aext[(size_t)row * K + kc + c0 + i * 4];
                    __half2 p0 = __floats2half2_rn(v.x, v.y);
                    __half2 p1 = __floats2half2_rn(v.z, v.w);
                    uint2 pk;
                    pk.x = *(unsigned int*)&p0;
                    pk.y = *(unsigned int*)&p1;
                    *(uint2*)&As[r][c0 + i * 4] = pk;
                }
            } else {
                #pragma unroll
                for (int i = 0; i < 4; i++) {
                    uint4 v = make_uint4(0, 0, 0, 0);
                    if (row < NN)
                        v = *(const uint4*)&g_h16[(size_t)row * K + kc + c0 + i * 8];
                    *(uint4*)&As[r][c0 + i * 8] = v;
                }
            }
        }
        {
            int r = tid >> 2;
            int c0 = (tid & 3) * 16;
            #pragma unroll
            for (int q = 0; q < 4; q++) {
                float4 v = *(const float4*)&W[(size_t)(kc + r) * HD + c0 + q * 4];
                __half2 p0 = __floats2half2_rn(v.x, v.y);
                __half2 p1 = __floats2half2_rn(v.z, v.w);
                uint2 pk;
                pk.x = *(unsigned int*)&p0;
                pk.y = *(unsigned int*)&p1;
                *(uint2*)&Bs[r][c0 + q * 4] = pk;
            }
        }
        __syncthreads();

        #pragma unroll
        for (int kk = 0; kk < 4; kk++) {
            uint32_t a0, a1, a2, a3;
            {
                int j = lane >> 3;
                uint32_t addr = smem_u32(&As[warp * 16 + (lane & 7) + 8 * (j & 1)]
                                            [kk * 16 + 8 * (j >> 1)]);
                asm volatile("ldmatrix.sync.aligned.m8n8.x4.shared.b16 {%0,%1,%2,%3}, [%4];"
                             : "=r"(a0), "=r"(a1), "=r"(a2), "=r"(a3) : "r"(addr));
            }
            #pragma unroll
            for (int nt = 0; nt < 8; nt += 2) {
                uint32_t b0, b1, b2, b3;
                int j = lane >> 3;
                uint32_t addr = smem_u32(&Bs[kk * 16 + (lane & 7) + 8 * (j & 1)]
                                            [nt * 8 + 8 * (j >> 1)]);
                asm volatile("ldmatrix.sync.aligned.m8n8.x4.trans.shared.b16 {%0,%1,%2,%3}, [%4];"
                             : "=r"(b0), "=r"(b1), "=r"(b2), "=r"(b3) : "r"(addr));
                asm volatile("mma.sync.aligned.m16n8k16.row.col.f32.f16.f16.f32 "
                             "{%0,%1,%2,%3}, {%4,%5,%6,%7}, {%8,%9}, {%0,%1,%2,%3};"
                             : "+f"(d[nt][0]), "+f"(d[nt][1]), "+f"(d[nt][2]), "+f"(d[nt][3])
                             : "r"(a0), "r"(a1), "r"(a2), "r"(a3), "r"(b0), "r"(b1));
                asm volatile("mma.sync.aligned.m16n8k16.row.col.f32.f16.f16.f32 "
                             "{%0,%1,%2,%3}, {%4,%5,%6,%7}, {%8,%9}, {%0,%1,%2,%3};"
                             : "+f"(d[nt+1][0]), "+f"(d[nt+1][1]), "+f"(d[nt+1][2]), "+f"(d[nt+1][3])
                             : "r"(a0), "r"(a1), "r"(a2), "r"(a3), "r"(b2), "r"(b3));
            }
        }
    }

    int g = lane >> 2, q = lane & 3;
    int row0 = brow + warp * 16 + g;
    int row1 = row0 + 8;
    float d0 = (row0 < NN) ? g_dis[row0] : 0.f;
    float d1 = (row1 < NN) ? g_dis[row1] : 0.f;
    #pragma unroll
    for (int nt = 0; nt < 8; nt++) {
        int c = nt * 8 + 2 * q;
        if (row0 < NN)
            *(float2*)&g_hn[(size_t)row0 * HD + c] = make_float2(d[nt][0] * d0, d[nt][1] * d0);
        if (row1 < NN)
            *(float2*)&g_hn[(size_t)row1 * HD + c] = make_float2(d[nt][2] * d1, d[nt][3] * d1);
    }
}

// ---------------- gather: paired-lane float4 gathers + aligned int4 colidx, pipelined ----------------
// lanes 0-15 gather even edge, lanes 16-31 odd edge; each lane owns 4 feature cols.
// Returns the full aggregated float4 (incl. self term) valid on lanes 0-15.
__device__ __forceinline__ float4 warp_gather_sum4(int v, int lane) {
    int beg = g_rowptr[v], end = g_rowptr[v + 1];   // both multiples of 4
    int col4 = (lane & 15) * 4;
    bool lo = lane < 16;
    float4 acc = make_float4(0.f, 0.f, 0.f, 0.f);

    int niter = (end - beg) >> 2;
    if (niter) {
        int4 c = *(const int4*)&g_colidx[beg];
        int p = beg + 4;
        for (int it = 1; it < niter; it++, p += 4) {
            int4 n = *(const int4*)&g_colidx[p];      // prefetch next 4 edges
            int u0 = lo ? c.x : c.y;
            int u1 = lo ? c.z : c.w;
            float4 t0 = *(const float4*)&g_hn[(size_t)u0 * HD + col4];
            float4 t1 = *(const float4*)&g_hn[(size_t)u1 * HD + col4];
            acc.x += t0.x + t1.x; acc.y += t0.y + t1.y;
            acc.z += t0.z + t1.z; acc.w += t0.w + t1.w;
            c = n;
        }
        int u0 = lo ? c.x : c.y;
        int u1 = lo ? c.z : c.w;
        float4 t0 = *(const float4*)&g_hn[(size_t)u0 * HD + col4];
        float4 t1 = *(const float4*)&g_hn[(size_t)u1 * HD + col4];
        acc.x += t0.x + t1.x; acc.y += t0.y + t1.y;
        acc.z += t0.z + t1.z; acc.w += t0.w + t1.w;
    }

    // fold odd-edge half onto lanes 0-15
    acc.x += __shfl_xor_sync(0xffffffffu, acc.x, 16);
    acc.y += __shfl_xor_sync(0xffffffffu, acc.y, 16);
    acc.z += __shfl_xor_sync(0xffffffffu, acc.z, 16);
    acc.w += __shfl_xor_sync(0xffffffffu, acc.w, 16);

    if (lo) {   // self-loop term
        float4 s = *(const float4*)&g_hn[(size_t)v * HD + col4];
        acc.x += s.x; acc.y += s.y; acc.z += s.z; acc.w += s.w;
    }
    return acc;
}

__global__ void __launch_bounds__(256, 8)
k_agg(const float* __restrict__ bias, int first) {
    int warp = (blockIdx.x * blockDim.x + threadIdx.x) >> 5;
    int lane = threadIdx.x & 31;
    if (warp >= NN) return;
    int v = warp;

    float4 acc = warp_gather_sum4(v, lane);
    if (lane < 16) {
        int col4 = lane * 4;
        float d = g_dis[v];
        float4 b = *(const float4*)&bias[col4];
        float h0 = fmaxf(fmaf(d, acc.x, b.x), 0.f);
        float h1 = fmaxf(fmaf(d, acc.y, b.y), 0.f);
        float h2 = fmaxf(fmaf(d, acc.z, b.z), 0.f);
        float h3 = fmaxf(fmaf(d, acc.w, b.w), 0.f);

        size_t fo = (size_t)v * HD + col4;
        __half2 p0 = __floats2half2_rn(h0, h1);
        __half2 p1 = __floats2half2_rn(h2, h3);
        uint2 pk;
        pk.x = *(unsigned int*)&p0;
        pk.y = *(unsigned int*)&p1;
        *(uint2*)&g_h16[fo] = pk;

        if (first) {
            *(float4*)&g_jk[fo] = make_float4(h0, h1, h2, h3);
        } else {
            float4 j = *(const float4*)&g_jk[fo];
            *(float4*)&g_jk[fo] = make_float4(fmaxf(j.x, h0), fmaxf(j.y, h1),
                                              fmaxf(j.z, h2), fmaxf(j.w, h3));
        }
    }
}

// ---------------- last layer fused with head ----------------
__global__ void __launch_bounds__(256, 8)
k_agg_proj(const float* __restrict__ bias,
           const float* __restrict__ fcw, const float* __restrict__ fcb,
           float* __restrict__ out) {
    __shared__ float Wsm[HD * CC];
    __shared__ float bsm[CC];
    int tid = threadIdx.x;
    for (int i = tid; i < HD * CC; i += blockDim.x) Wsm[i] = fcw[i];
    if (tid < CC) bsm[tid] = fcb[tid];
    __syncthreads();

    int warp = (blockIdx.x * blockDim.x + tid) >> 5;
    int lane = tid & 31;
    if (warp >= NN) return;
    int v = warp;

    float4 acc = warp_gather_sum4(v, lane);
    float4 jv = make_float4(0.f, 0.f, 0.f, 0.f);
    if (lane < 16) {
        int col4 = lane * 4;
        float d = g_dis[v];
        float4 b = *(const float4*)&bias[col4];
        float h0 = fmaxf(fmaf(d, acc.x, b.x), 0.f);
        float h1 = fmaxf(fmaf(d, acc.y, b.y), 0.f);
        float h2 = fmaxf(fmaf(d, acc.z, b.z), 0.f);
        float h3 = fmaxf(fmaf(d, acc.w, b.w), 0.f);
        float4 j = *(const float4*)&g_jk[(size_t)v * HD + col4];
        jv = make_float4(fmaxf(j.x, h0), fmaxf(j.y, h1), fmaxf(j.z, h2), fmaxf(j.w, h3));
    }

    // projection: jk cols live 4/lane on lanes 0-15
    bool act = lane < 20;
    int c0 = lane * 2;
    float a0 = 0.f, a1 = 0.f;
    #pragma unroll
    for (int k = 0; k < HD; k++) {
        float comp = ((k & 3) == 0) ? jv.x : ((k & 3) == 1) ? jv.y
                   : ((k & 3) == 2) ? jv.z : jv.w;             // compile-time select (unrolled)
        float hv = __shfl_sync(0xffffffffu, comp, k >> 2);
        if (act) {
            float2 w = *(const float2*)&Wsm[k * CC + c0];
            a0 = fmaf(hv, w.x, a0);
            a1 = fmaf(hv, w.y, a1);
        }
    }
    if (act) { a0 += bsm[c0]; a1 += bsm[c0 + 1]; }

    float m = act ? fmaxf(a0, a1) : -INFINITY;
    #pragma unroll
    for (int off = 16; off; off >>= 1) m = fmaxf(m, __shfl_xor_sync(0xffffffffu, m, off));
    float s = act ? (expf(a0 - m) + expf(a1 - m)) : 0.f;
    #pragma unroll
    for (int off = 16; off; off >>= 1) s += __shfl_xor_sync(0xffffffffu, s, off);
    float lse = m + logf(s);

    if (act) {
        float2 o = make_float2(a0 - lse, a1 - lse);
        *(float2*)&out[(size_t)v * CC + c0] = o;
    }
}

// ---------------- launch ----------------
extern "C" void kernel_launch(void* const* d_in, const int* in_sizes, int n_in,
                              void* d_out, int out_size) {
    const float* x   = (const float*)d_in[0];
    const int*   ei  = (const int*)  d_in[1];
    const float* W0  = (const float*)d_in[2];
    const float* Ws  = (const float*)d_in[3];
    const float* bs  = (const float*)d_in[4];
    const float* fcw = (const float*)d_in[5];
    const float* fcb = (const float*)d_in[6];
    float* out = (float*)d_out;

    const int* src = ei;         // edge_index[0]
    const int* dst = ei + EE;    // edge_index[1]

    int* degp;
    cudaGetSymbolAddress((void**)&degp, g_deg);

    // CSR build (padded to multiples of 4 per node)
    cudaMemsetAsync(degp, 0, NN * sizeof(int));
    k_count  <<<(EE / 4 + 255) / 256, 256>>>(dst);
    k_scan1  <<<NB, 256>>>();
    k_scan2  <<<1, 512>>>();
    k_scan3  <<<NB, 256>>>();
    k_scatter<<<(EE / 4 + 255) / 256, 256>>>(src, dst);
    k_pad    <<<NB, 256>>>();

    const int GEMM_GRID = (NN + 127) / 128;  // 782 (128-row tiles)
    const int AGG_GRID  = (NN + 7) / 8;      // 8 warps per 256-thread block

    // layer 0: x (N x 128) @ W0
    k_gemm_mma<FIN, true><<<GEMM_GRID, 256>>>(x, W0);
    k_agg<<<AGG_GRID, 256>>>(bs + 0 * HD, 1);

    // layers 1..4
    for (int l = 1; l < LL - 1; l++) {
        k_gemm_mma<HD, false><<<GEMM_GRID, 256>>>(nullptr, Ws + (size_t)(l - 1) * HD * HD);
        k_agg<<<AGG_GRID, 256>>>(bs + (size_t)l * HD, 0);
    }
    // layer 5: aggregation fused with projection head
    k_gemm_mma<HD, false><<<GEMM_GRID, 256>>>(nullptr, Ws + (size_t)(LL - 2) * HD * HD);
    k_agg_proj<<<AGG_GRID, 256>>>(bs + (size_t)(LL - 1) * HD, fcw, fcb, out);
}